// round 1
// baseline (speedup 1.0000x reference)
#include <cuda_runtime.h>
#include <cstdint>

#define N_DRUG 846
#define DIM 256
#define KNB 128

// ---------------- scratch (device globals; no allocation allowed) -------------
__device__ float g_w2sum[N_DRUG * DIM];
__device__ float g_b2sum[KNB];
__device__ float g_weighted[N_DRUG * DIM];
__device__ float g_x[N_DRUG * DIM];
__device__ float g_sum[DIM];
__device__ float g_sumsq[DIM];

// ---------------- packed fp32x2 helpers (sm_103a FFMA2 path) ------------------
__device__ __forceinline__ unsigned long long pack2(float x) {
    unsigned long long r;
    asm("mov.b64 %0, {%1, %1};" : "=l"(r) : "f"(x));
    return r;
}
__device__ __forceinline__ unsigned long long fma2(unsigned long long a,
                                                   unsigned long long b,
                                                   unsigned long long c) {
    unsigned long long d;
    asm("fma.rn.f32x2 %0, %1, %2, %3;" : "=l"(d) : "l"(a), "l"(b), "l"(c));
    return d;
}
__device__ __forceinline__ float2 unpack2(unsigned long long v) {
    float2 r;
    asm("mov.b64 {%0, %1}, %2;" : "=f"(r.x), "=f"(r.y) : "l"(v));
    return r;
}

// ---------------- k0: zero BN stats + b2sum[k] = sum_e b2[k,e] ----------------
__global__ void k_init(const float* __restrict__ b2) {
    int t = threadIdx.x;
    g_sum[t] = 0.f;
    g_sumsq[t] = 0.f;
    int w = t >> 5, lane = t & 31;
    for (int k = w; k < KNB; k += 8) {
        const float4* row = reinterpret_cast<const float4*>(b2 + k * DIM);
        float4 a = row[lane];
        float4 bq = row[lane + 32];
        float s = a.x + a.y + a.z + a.w + bq.x + bq.y + bq.z + bq.w;
        #pragma unroll
        for (int m = 16; m; m >>= 1) s += __shfl_xor_sync(0xffffffffu, s, m);
        if (lane == 0) g_b2sum[k] = s;
    }
}

// ---------------- k1: w2sum[n,d] = sum_e W2[n,d,e]  (streams 222 MB) ----------
__global__ void __launch_bounds__(256) k_w2sum(const float* __restrict__ W2) {
    int n = blockIdx.x;
    const float* Wn = W2 + (size_t)n * (DIM * DIM);
    int w = threadIdx.x >> 5, lane = threadIdx.x & 31;
    for (int d = w; d < DIM; d += 8) {
        const float4* row = reinterpret_cast<const float4*>(Wn + d * DIM);
        float4 a = row[lane];
        float4 bq = row[lane + 32];
        float s = a.x + a.y + a.z + a.w + bq.x + bq.y + bq.z + bq.w;
        #pragma unroll
        for (int m = 16; m; m >>= 1) s += __shfl_xor_sync(0xffffffffu, s, m);
        if (lane == 0) g_w2sum[n * DIM + d] = s;
    }
}

// ---------------- k2: per-drug fused GEMM + softmax + weighted gather ---------
// h1[k,e] = relu( sum_d A[k,d]*W1[n,d,e] + b1[k,e] ),  A[k,d]=drug[d]*rela[rel_k,d]
// logit[k] = sum_e h1[k,e]*w2sum[n,e] + b2sum[k];  p = softmax_k(logit)
// weighted[n,d] = sum_k p[k]*ent[tail_k,d]
__global__ void __launch_bounds__(256) k_main(
    const int* __restrict__ drug_name, const int* __restrict__ adj_tail,
    const int* __restrict__ adj_rel, const float* __restrict__ drug_table,
    const float* __restrict__ rela_table, const float* __restrict__ ent_table,
    const float* __restrict__ W1, const float* __restrict__ b1) {
    __shared__ __align__(16) unsigned long long As2[KNB][32];  // A packed {a,a}
    __shared__ __align__(16) float Ws[32][64];                 // W1 tile [dd][e]
    __shared__ float s_drug[DIM];
    __shared__ float s_w2[DIM];
    __shared__ int s_rel[KNB];
    __shared__ int s_tail[KNB];
    __shared__ float s_logit[KNB];
    __shared__ float s_red[8];
    __shared__ float s_scalar;

    int n = blockIdx.x;
    int tid = threadIdx.x;
    int tx = tid & 15, ty = tid >> 4;
    int lane = tid & 31, wrp = tid >> 5;

    int dn = drug_name[n];
    s_drug[tid] = drug_table[dn * DIM + tid];
    s_w2[tid] = g_w2sum[n * DIM + tid];
    if (tid < KNB) {
        s_rel[tid] = adj_rel[n * KNB + tid];
        s_tail[tid] = adj_tail[n * KNB + tid];
        s_logit[tid] = g_b2sum[tid];
    }
    __syncthreads();

    const float* W1n = W1 + (size_t)n * (DIM * DIM);

    for (int e0 = 0; e0 < DIM; e0 += 64) {
        unsigned long long acc[8][2];
        #pragma unroll
        for (int i = 0; i < 8; i++) { acc[i][0] = 0ull; acc[i][1] = 0ull; }

        for (int dc = 0; dc < DIM; dc += 32) {
            __syncthreads();
            // stage A tile (gather from L2-resident rela_table), packed {a,a}
            #pragma unroll
            for (int p = 0; p < 16; p++) {
                int idx = tid + p * 256;
                int dd = idx & 31, k = idx >> 5;
                float a = s_drug[dc + dd] * rela_table[s_rel[k] * DIM + dc + dd];
                As2[k][dd] = pack2(a);
            }
            // stage W1 tile
            #pragma unroll
            for (int p = 0; p < 8; p++) {
                int idx = tid + p * 256;
                int e = idx & 63, dd = idx >> 6;
                Ws[dd][e] = W1n[(dc + dd) * DIM + e0 + e];
            }
            __syncthreads();
            // 8k x 4e register tile, packed fp32x2 FMA
            #pragma unroll 16
            for (int dd = 0; dd < 32; dd++) {
                ulonglong2 w = *reinterpret_cast<const ulonglong2*>(&Ws[dd][tx * 4]);
                #pragma unroll
                for (int i = 0; i < 8; i++) {
                    unsigned long long a2 = As2[ty * 8 + i][dd];
                    acc[i][0] = fma2(a2, w.x, acc[i][0]);
                    acc[i][1] = fma2(a2, w.y, acc[i][1]);
                }
            }
        }
        // epilogue: relu(+b1) then dot with w2sum, reduce across tx into logits
        float w0 = s_w2[e0 + tx * 4 + 0];
        float w1 = s_w2[e0 + tx * 4 + 1];
        float w2v = s_w2[e0 + tx * 4 + 2];
        float w3 = s_w2[e0 + tx * 4 + 3];
        #pragma unroll
        for (int i = 0; i < 8; i++) {
            int k = ty * 8 + i;
            float4 bb = *reinterpret_cast<const float4*>(&b1[k * DIM + e0 + tx * 4]);
            float2 a0 = unpack2(acc[i][0]);
            float2 a1 = unpack2(acc[i][1]);
            float part = fmaxf(a0.x + bb.x, 0.f) * w0 + fmaxf(a0.y + bb.y, 0.f) * w1 +
                         fmaxf(a1.x + bb.z, 0.f) * w2v + fmaxf(a1.y + bb.w, 0.f) * w3;
            part += __shfl_xor_sync(0xffffffffu, part, 8);
            part += __shfl_xor_sync(0xffffffffu, part, 4);
            part += __shfl_xor_sync(0xffffffffu, part, 2);
            part += __shfl_xor_sync(0xffffffffu, part, 1);
            if (tx == 0) atomicAdd(&s_logit[k], part);
        }
    }
    __syncthreads();

    // softmax over 128 logits
    float v = (tid < KNB) ? s_logit[tid] : -1e30f;
    #pragma unroll
    for (int m = 16; m; m >>= 1) v = fmaxf(v, __shfl_xor_sync(0xffffffffu, v, m));
    if (lane == 0) s_red[wrp] = v;
    __syncthreads();
    if (tid == 0) {
        float mm = s_red[0];
        #pragma unroll
        for (int i = 1; i < 8; i++) mm = fmaxf(mm, s_red[i]);
        s_scalar = mm;
    }
    __syncthreads();
    float mm = s_scalar;
    float ev = (tid < KNB) ? expf(s_logit[tid] - mm) : 0.f;
    float sv = ev;
    #pragma unroll
    for (int m = 16; m; m >>= 1) sv += __shfl_xor_sync(0xffffffffu, sv, m);
    if (lane == 0) s_red[wrp] = sv;
    __syncthreads();
    if (tid == 0) {
        float ss = 0.f;
        #pragma unroll
        for (int i = 0; i < 8; i++) ss += s_red[i];
        s_scalar = 1.f / ss;
    }
    __syncthreads();
    if (tid < KNB) s_logit[tid] = ev * s_scalar;
    __syncthreads();

    // weighted entity aggregation: thread owns feature d = tid
    float wacc = 0.f;
    #pragma unroll 4
    for (int k = 0; k < KNB; k++)
        wacc += s_logit[k] * ent_table[(size_t)s_tail[k] * DIM + tid];
    g_weighted[n * DIM + tid] = wacc;
}

// ---------------- k4: x = relu([weighted, drug] @ lin_w^T + lin_b) + BN stats -
__global__ void __launch_bounds__(256) k_linear(
    const int* __restrict__ drug_name, const float* __restrict__ drug_table,
    const float* __restrict__ lin_w, const float* __restrict__ lin_b) {
    __shared__ float s_in[6][512];
    __shared__ float s_w[256][33];
    int tid = threadIdx.x;
    int n0 = blockIdx.x * 6;

    #pragma unroll
    for (int p = 0; p < 12; p++) {
        int idx = tid + p * 256;
        int b = idx >> 9, i = idx & 511;
        float val;
        if (i < 256) val = g_weighted[(n0 + b) * DIM + i];
        else val = drug_table[drug_name[n0 + b] * DIM + (i - 256)];
        s_in[b][i] = val;
    }

    float acc[6] = {0.f, 0.f, 0.f, 0.f, 0.f, 0.f};
    for (int i0 = 0; i0 < 512; i0 += 32) {
        __syncthreads();
        #pragma unroll
        for (int p = 0; p < 32; p++) {
            int j = (tid >> 5) + p * 8;
            int ii = tid & 31;
            s_w[j][ii] = lin_w[j * 512 + i0 + ii];
        }
        __syncthreads();
        #pragma unroll
        for (int ii = 0; ii < 32; ii++) {
            float w = s_w[tid][ii];
            #pragma unroll
            for (int b = 0; b < 6; b++) acc[b] += s_in[b][i0 + ii] * w;
        }
    }
    float bj = lin_b[tid];
    float s = 0.f, sq = 0.f;
    #pragma unroll
    for (int b = 0; b < 6; b++) {
        float x = fmaxf(acc[b] + bj, 0.f);
        g_x[(n0 + b) * DIM + tid] = x;
        s += x;
        sq += x * x;
    }
    atomicAdd(&g_sum[tid], s);
    atomicAdd(&g_sumsq[tid], sq);
}

// ---------------- k5: BatchNorm finalize --------------------------------------
__global__ void k_bn(const float* __restrict__ gamma, const float* __restrict__ beta,
                     float* __restrict__ out) {
    int n = blockIdx.x, j = threadIdx.x;
    const float inv_n = 1.f / 846.f;
    float mean = g_sum[j] * inv_n;
    float var = g_sumsq[j] * inv_n - mean * mean;
    float rstd = rsqrtf(var + 1e-5f);
    out[n * DIM + j] = gamma[j] * (g_x[n * DIM + j] - mean) * rstd + beta[j];
}

// ---------------- launch -------------------------------------------------------
extern "C" void kernel_launch(void* const* d_in, const int* in_sizes, int n_in,
                              void* d_out, int out_size) {
    const int* drug_name = (const int*)d_in[0];
    const int* adj_tail = (const int*)d_in[1];
    const int* adj_rel = (const int*)d_in[2];
    const float* drug_table = (const float*)d_in[3];
    const float* rela_table = (const float*)d_in[4];
    const float* ent_table = (const float*)d_in[5];
    const float* W1 = (const float*)d_in[6];
    const float* b1 = (const float*)d_in[7];
    const float* W2 = (const float*)d_in[8];
    const float* b2 = (const float*)d_in[9];
    const float* lin_w = (const float*)d_in[10];
    const float* lin_b = (const float*)d_in[11];
    const float* gamma = (const float*)d_in[12];
    const float* beta = (const float*)d_in[13];
    float* out = (float*)d_out;

    k_init<<<1, 256>>>(b2);
    k_w2sum<<<N_DRUG, 256>>>(W2);
    k_main<<<N_DRUG, 256>>>(drug_name, adj_tail, adj_rel, drug_table, rela_table,
                            ent_table, W1, b1);
    k_linear<<<141, 256>>>(drug_name, drug_table, lin_w, lin_b);
    k_bn<<<N_DRUG, 256>>>(gamma, beta, out);
}

// round 3
// speedup vs baseline: 2.6423x; 2.6423x over previous
#include <cuda_runtime.h>
#include <cuda_fp16.h>
#include <cstdint>

#define N_DRUG 846
#define DIM 256
#define KNB 128

// ---------------- scratch (device globals; no allocation allowed) -------------
__device__ float g_w2sum[N_DRUG * DIM];
__device__ float g_b2sum[KNB];
__device__ float g_lpart[N_DRUG * 256];     // [n][half][128]
__device__ float g_weighted[N_DRUG * DIM];
__device__ float g_x[N_DRUG * DIM];
__device__ float g_sum[DIM];
__device__ float g_sumsq[DIM];

// ---------------- warp-level mma (baseline PTX, sm_80+) ------------------------
__device__ __forceinline__ void mma16816(float* c, const uint32_t* a,
                                         uint32_t b0, uint32_t b1) {
    asm volatile(
        "mma.sync.aligned.m16n8k16.row.col.f32.f16.f16.f32 "
        "{%0,%1,%2,%3}, {%4,%5,%6,%7}, {%8,%9}, {%0,%1,%2,%3};"
        : "+f"(c[0]), "+f"(c[1]), "+f"(c[2]), "+f"(c[3])
        : "r"(a[0]), "r"(a[1]), "r"(a[2]), "r"(a[3]), "r"(b0), "r"(b1));
}

// ---------------- k0: zero BN stats + b2sum[k] = sum_e b2[k,e] ----------------
__global__ void k_init(const float* __restrict__ b2) {
    int t = threadIdx.x;
    g_sum[t] = 0.f;
    g_sumsq[t] = 0.f;
    int w = t >> 5, lane = t & 31;
    for (int k = w; k < KNB; k += 8) {
        const float4* row = reinterpret_cast<const float4*>(b2 + k * DIM);
        float4 a = row[lane];
        float4 bq = row[lane + 32];
        float s = a.x + a.y + a.z + a.w + bq.x + bq.y + bq.z + bq.w;
        #pragma unroll
        for (int m = 16; m; m >>= 1) s += __shfl_xor_sync(0xffffffffu, s, m);
        if (lane == 0) g_b2sum[k] = s;
    }
}

// ---------------- k1: w2sum[n,d] = sum_e W2[n,d,e]  (streams 222 MB) ----------
__global__ void __launch_bounds__(256) k_w2sum(const float* __restrict__ W2) {
    int n = blockIdx.x;
    const float* Wn = W2 + (size_t)n * (DIM * DIM);
    int w = threadIdx.x >> 5, lane = threadIdx.x & 31;
    for (int d = w; d < DIM; d += 8) {
        const float4* row = reinterpret_cast<const float4*>(Wn + d * DIM);
        float4 a = row[lane];
        float4 bq = row[lane + 32];
        float s = a.x + a.y + a.z + a.w + bq.x + bq.y + bq.z + bq.w;
        #pragma unroll
        for (int m = 16; m; m >>= 1) s += __shfl_xor_sync(0xffffffffu, s, m);
        if (lane == 0) g_w2sum[n * DIM + d] = s;
    }
}

// ---------------- k2: partial logits via fp16-split mma.sync ------------------
// CTA (n, eh): h1[k, e0:e0+128] = A[128 x 256] @ W1n[:, e0:e0+128]
// lpart[k] = sum_e relu(h1 + b1) * w2sum   (over this CTA's 128 e-columns)
static constexpr int ROWB = 144;            // 72 halves, conflict-free stride
static constexpr int A_HI = 0;              // 128 rows
static constexpr int A_LO = A_HI + 128 * ROWB;
static constexpr int B_HI = A_LO + 128 * ROWB;  // 128 e-rows
static constexpr int B_LO = B_HI + 128 * ROWB;
static constexpr int SM_DRUG = B_LO + 128 * ROWB;       // 256 f32
static constexpr int SM_W2 = SM_DRUG + 1024;            // 128 f32
static constexpr int SM_REL = SM_W2 + 512;              // 128 int
static constexpr int SM_LP = SM_REL + 512;              // 128 f32
static constexpr int SMEM_TOTAL = SM_LP + 512;

__global__ void __launch_bounds__(256, 2) k_logits(
    const int* __restrict__ drug_name, const int* __restrict__ adj_rel,
    const float* __restrict__ drug_table, const float* __restrict__ rela_table,
    const float* __restrict__ W1, const float* __restrict__ b1p) {
    extern __shared__ char smem[];
    float* s_drug = (float*)(smem + SM_DRUG);
    float* s_w2 = (float*)(smem + SM_W2);
    int* s_rel = (int*)(smem + SM_REL);
    float* s_lp = (float*)(smem + SM_LP);

    int n = blockIdx.x, eh = blockIdx.y;
    int e0 = eh * 128;
    int tid = threadIdx.x;
    int wid = tid >> 5, lane = tid & 31;
    int g = lane >> 2, tg = lane & 3;
    int m0 = (wid & 3) * 32;        // warp's 32 k-rows
    int n0 = (wid >> 2) * 64;       // warp's 64 e-cols (within the 128 half)

    int dn = drug_name[n];
    s_drug[tid] = drug_table[dn * DIM + tid];
    if (tid < KNB) {
        s_w2[tid] = g_w2sum[n * DIM + e0 + tid];
        s_rel[tid] = adj_rel[n * KNB + tid];
        s_lp[tid] = 0.f;
    }
    __syncthreads();

    const float* W1n = W1 + (size_t)n * (DIM * DIM);
    float c[2][8][4];
    #pragma unroll
    for (int mt = 0; mt < 2; mt++)
        #pragma unroll
        for (int nt = 0; nt < 8; nt++)
            #pragma unroll
            for (int q = 0; q < 4; q++) c[mt][nt][q] = 0.f;

    for (int ch = 0; ch < 4; ch++) {
        int dc = ch * 64;
        if (ch) __syncthreads();

        // ---- stage A chunk: A[k][dd] = drug[dc+dd]*rela[rel_k][dc+dd], split
        #pragma unroll
        for (int it = 0; it < 16; it++) {
            int idx = tid + it * 256;
            int k = idx >> 5;
            int dd = (idx & 31) * 2;
            float2 rv = *(const float2*)(rela_table + (size_t)s_rel[k] * DIM + dc + dd);
            float a0 = s_drug[dc + dd] * rv.x;
            float a1 = s_drug[dc + dd + 1] * rv.y;
            __half h0 = __float2half_rn(a0), h1 = __float2half_rn(a1);
            float l0 = a0 - __half2float(h0), l1 = a1 - __half2float(h1);
            *(__half2*)(smem + A_HI + k * ROWB + dd * 2) = __halves2half2(h0, h1);
            *(__half2*)(smem + A_LO + k * ROWB + dd * 2) =
                __halves2half2(__float2half_rn(l0), __float2half_rn(l1));
        }
        // ---- stage B chunk: B[e][dd] = W1n[dc+dd][e0+e], split
        #pragma unroll
        for (int it = 0; it < 16; it++) {
            int idx = tid + it * 256;
            int e = idx & 127;
            int dd = (idx >> 7) * 2;
            const float* wp = W1n + (size_t)(dc + dd) * DIM + e0 + e;
            float w0 = wp[0], w1 = wp[DIM];
            __half h0 = __float2half_rn(w0), h1 = __float2half_rn(w1);
            float l0 = w0 - __half2float(h0), l1 = w1 - __half2float(h1);
            *(__half2*)(smem + B_HI + e * ROWB + dd * 2) = __halves2half2(h0, h1);
            *(__half2*)(smem + B_LO + e * ROWB + dd * 2) =
                __halves2half2(__float2half_rn(l0), __float2half_rn(l1));
        }
        __syncthreads();

        // ---- compute: 4 k-steps of 16
        #pragma unroll
        for (int ks = 0; ks < 4; ks++) {
            int kb = ks * 32 + tg * 4;  // byte offset along a row
            uint32_t ah[2][4], al[2][4];
            #pragma unroll
            for (int mt = 0; mt < 2; mt++) {
                const char* base = smem + (m0 + mt * 16 + g) * ROWB + kb;
                ah[mt][0] = *(const uint32_t*)(base + A_HI);
                ah[mt][1] = *(const uint32_t*)(base + A_HI + 8 * ROWB);
                ah[mt][2] = *(const uint32_t*)(base + A_HI + 16);
                ah[mt][3] = *(const uint32_t*)(base + A_HI + 8 * ROWB + 16);
                al[mt][0] = *(const uint32_t*)(base + A_LO);
                al[mt][1] = *(const uint32_t*)(base + A_LO + 8 * ROWB);
                al[mt][2] = *(const uint32_t*)(base + A_LO + 16);
                al[mt][3] = *(const uint32_t*)(base + A_LO + 8 * ROWB + 16);
            }
            #pragma unroll
            for (int nt = 0; nt < 8; nt++) {
                const char* bb = smem + (n0 + nt * 8 + g) * ROWB + kb;
                uint32_t bh0 = *(const uint32_t*)(bb + B_HI);
                uint32_t bh1 = *(const uint32_t*)(bb + B_HI + 16);
                uint32_t bl0 = *(const uint32_t*)(bb + B_LO);
                uint32_t bl1 = *(const uint32_t*)(bb + B_LO + 16);
                mma16816(c[0][nt], ah[0], bh0, bh1);
                mma16816(c[1][nt], ah[1], bh0, bh1);
                mma16816(c[0][nt], ah[0], bl0, bl1);
                mma16816(c[1][nt], ah[1], bl0, bl1);
                mma16816(c[0][nt], al[0], bh0, bh1);
                mma16816(c[1][nt], al[1], bh0, bh1);
            }
        }
    }

    // ---- epilogue: +b1, relu, dot w2sum; deterministic reduction
    float lg[2][2] = {{0.f, 0.f}, {0.f, 0.f}};
    #pragma unroll
    for (int mt = 0; mt < 2; mt++) {
        int r0 = m0 + mt * 16 + g;
        #pragma unroll
        for (int nt = 0; nt < 8; nt++) {
            int ecl = n0 + nt * 8 + tg * 2;
            float w0 = s_w2[ecl], w1 = s_w2[ecl + 1];
            float2 b00 = *(const float2*)(b1p + (size_t)r0 * DIM + e0 + ecl);
            float2 b01 = *(const float2*)(b1p + (size_t)(r0 + 8) * DIM + e0 + ecl);
            lg[mt][0] += fmaxf(c[mt][nt][0] + b00.x, 0.f) * w0 +
                         fmaxf(c[mt][nt][1] + b00.y, 0.f) * w1;
            lg[mt][1] += fmaxf(c[mt][nt][2] + b01.x, 0.f) * w0 +
                         fmaxf(c[mt][nt][3] + b01.y, 0.f) * w1;
        }
    }
    #pragma unroll
    for (int mt = 0; mt < 2; mt++)
        #pragma unroll
        for (int h = 0; h < 2; h++) {
            float v = lg[mt][h];
            v += __shfl_xor_sync(0xffffffffu, v, 1);
            v += __shfl_xor_sync(0xffffffffu, v, 2);
            if (tg == 0)
                atomicAdd(&s_lp[m0 + mt * 16 + h * 8 + g], v);  // 2 contributors
        }
    __syncthreads();
    if (tid < KNB) g_lpart[n * 256 + eh * 128 + tid] = s_lp[tid];
}

// ---------------- k3: softmax over neighbors + weighted entity gather ---------
__global__ void __launch_bounds__(256) k_softgather(
    const int* __restrict__ adj_tail, const float* __restrict__ ent_table) {
    __shared__ float s_logit[KNB];
    __shared__ int s_tail[KNB];
    __shared__ float s_red[8];
    __shared__ float s_scalar;
    int n = blockIdx.x, tid = threadIdx.x;
    int wid = tid >> 5, lane = tid & 31;

    if (tid < KNB) {
        s_logit[tid] = g_lpart[n * 256 + tid] + g_lpart[n * 256 + 128 + tid] +
                       g_b2sum[tid];
        s_tail[tid] = adj_tail[n * KNB + tid];
    }
    __syncthreads();

    float v = (tid < KNB) ? s_logit[tid] : -1e30f;
    #pragma unroll
    for (int m = 16; m; m >>= 1) v = fmaxf(v, __shfl_xor_sync(0xffffffffu, v, m));
    if (lane == 0) s_red[wid] = v;
    __syncthreads();
    if (tid == 0) {
        float mm = s_red[0];
        #pragma unroll
        for (int i = 1; i < 8; i++) mm = fmaxf(mm, s_red[i]);
        s_scalar = mm;
    }
    __syncthreads();
    float mm = s_scalar;
    float ev = (tid < KNB) ? expf(s_logit[tid] - mm) : 0.f;
    float sv = ev;
    #pragma unroll
    for (int m = 16; m; m >>= 1) sv += __shfl_xor_sync(0xffffffffu, sv, m);
    if (lane == 0) s_red[wid] = sv;
    __syncthreads();
    if (tid == 0) {
        float ss = 0.f;
        #pragma unroll
        for (int i = 0; i < 8; i++) ss += s_red[i];
        s_scalar = 1.f / ss;
    }
    __syncthreads();
    if (tid < KNB) s_logit[tid] = ev * s_scalar;
    __syncthreads();

    float wacc = 0.f;
    #pragma unroll 4
    for (int k = 0; k < KNB; k++)
        wacc += s_logit[k] * __ldg(&ent_table[(size_t)s_tail[k] * DIM + tid]);
    g_weighted[n * DIM + tid] = wacc;
}

// ---------------- k4: x = relu([weighted, drug] @ lin_w^T + lin_b) + BN stats -
__global__ void __launch_bounds__(256) k_linear(
    const int* __restrict__ drug_name, const float* __restrict__ drug_table,
    const float* __restrict__ lin_w, const float* __restrict__ lin_b) {
    __shared__ float s_in[3][512];
    __shared__ float s_w[256][33];
    int tid = threadIdx.x;
    int n0 = blockIdx.x * 3;

    #pragma unroll
    for (int p = 0; p < 6; p++) {
        int idx = tid + p * 256;
        int b = idx >> 9, i = idx & 511;
        float val;
        if (i < 256) val = g_weighted[(n0 + b) * DIM + i];
        else val = drug_table[drug_name[n0 + b] * DIM + (i - 256)];
        s_in[b][i] = val;
    }

    float acc[3] = {0.f, 0.f, 0.f};
    for (int i0 = 0; i0 < 512; i0 += 32) {
        __syncthreads();
        #pragma unroll
        for (int p = 0; p < 32; p++) {
            int j = (tid >> 5) + p * 8;
            int ii = tid & 31;
            s_w[j][ii] = lin_w[j * 512 + i0 + ii];
        }
        __syncthreads();
        #pragma unroll
        for (int ii = 0; ii < 32; ii++) {
            float w = s_w[tid][ii];
            #pragma unroll
            for (int b = 0; b < 3; b++) acc[b] += s_in[b][i0 + ii] * w;
        }
    }
    float bj = lin_b[tid];
    float s = 0.f, sq = 0.f;
    #pragma unroll
    for (int b = 0; b < 3; b++) {
        float x = fmaxf(acc[b] + bj, 0.f);
        g_x[(n0 + b) * DIM + tid] = x;
        s += x;
        sq += x * x;
    }
    atomicAdd(&g_sum[tid], s);
    atomicAdd(&g_sumsq[tid], sq);
}

// ---------------- k5: BatchNorm finalize --------------------------------------
__global__ void k_bn(const float* __restrict__ gamma, const float* __restrict__ beta,
                     float* __restrict__ out) {
    int n = blockIdx.x, j = threadIdx.x;
    const float inv_n = 1.f / 846.f;
    float mean = g_sum[j] * inv_n;
    float var = g_sumsq[j] * inv_n - mean * mean;
    float rstd = rsqrtf(var + 1e-5f);
    out[n * DIM + j] = gamma[j] * (g_x[n * DIM + j] - mean) * rstd + beta[j];
}

// ---------------- launch -------------------------------------------------------
extern "C" void kernel_launch(void* const* d_in, const int* in_sizes, int n_in,
                              void* d_out, int out_size) {
    const int* drug_name = (const int*)d_in[0];
    const int* adj_tail = (const int*)d_in[1];
    const int* adj_rel = (const int*)d_in[2];
    const float* drug_table = (const float*)d_in[3];
    const float* rela_table = (const float*)d_in[4];
    const float* ent_table = (const float*)d_in[5];
    const float* W1 = (const float*)d_in[6];
    const float* b1 = (const float*)d_in[7];
    const float* W2 = (const float*)d_in[8];
    const float* b2 = (const float*)d_in[9];
    const float* lin_w = (const float*)d_in[10];
    const float* lin_b = (const float*)d_in[11];
    const float* gamma = (const float*)d_in[12];
    const float* beta = (const float*)d_in[13];
    float* out = (float*)d_out;

    static int configured = 0;
    if (!configured) {
        cudaFuncSetAttribute(k_logits, cudaFuncAttributeMaxDynamicSharedMemorySize,
                             SMEM_TOTAL);
        configured = 1;
    }

    k_init<<<1, 256>>>(b2);
    k_w2sum<<<N_DRUG, 256>>>(W2);
    dim3 grid_l(N_DRUG, 2);
    k_logits<<<grid_l, 256, SMEM_TOTAL>>>(drug_name, adj_rel, drug_table,
                                          rela_table, W1, b1);
    k_softgather<<<N_DRUG, 256>>>(adj_tail, ent_table);
    k_linear<<<282, 256>>>(drug_name, drug_table, lin_w, lin_b);
    k_bn<<<N_DRUG, 256>>>(gamma, beta, out);
}